// round 10
// baseline (speedup 1.0000x reference)
#include <cuda_runtime.h>
#include <cuda_fp16.h>
#include <math.h>
#include <stdint.h>

#define B_ 16
#define D_ 512
#define K_ 64
#define N_ 4096
#define NSPLIT 4

// ---------------- scratch -----------------------------------------------------
__device__ __half g_Shf[(size_t)B_ * K_ * N_];                // softmax scores fp16 [b][k][n]
__device__ __half g_parth[(size_t)NSPLIT * B_ * D_ * K_];     // agg partials fp16 [ns][b][d][k]
__device__ float g_ssum[B_ * K_];
__device__ float g_bnorm[B_];

__device__ __forceinline__ unsigned smem_u32(const void* p) {
    unsigned a;
    asm("{ .reg .u64 t; cvta.to.shared.u64 t, %1; cvt.u32.u64 %0, t; }" : "=r"(a) : "l"(p));
    return a;
}

#define LDMX4(dst, addr) \
    asm volatile("ldmatrix.sync.aligned.m8n8.x4.shared.b16 {%0,%1,%2,%3}, [%4];" \
        : "=r"((dst)[0]), "=r"((dst)[1]), "=r"((dst)[2]), "=r"((dst)[3]) : "r"(addr))
#define LDMX4T(dst, addr) \
    asm volatile("ldmatrix.sync.aligned.m8n8.x4.trans.shared.b16 {%0,%1,%2,%3}, [%4];" \
        : "=r"((dst)[0]), "=r"((dst)[1]), "=r"((dst)[2]), "=r"((dst)[3]) : "r"(addr))
// f16 inputs, f16 accumulate (2 packed regs)
#define MMAH(hacc, a, b0, b1) \
    asm volatile("mma.sync.aligned.m16n8k16.row.col.f16.f16.f16.f16 " \
        "{%0,%1}, {%2,%3,%4,%5}, {%6,%7}, {%0,%1};" \
        : "+r"((hacc)[0]), "+r"((hacc)[1]) \
        : "r"((a)[0]), "r"((a)[1]), "r"((a)[2]), "r"((a)[3]), "r"(b0), "r"(b1))

// promote packed f16x2 pair into 4 f32 accumulators and rezero
__device__ __forceinline__ void promo(float* f, unsigned* h) {
    float2 lo = __half22float2(*reinterpret_cast<__half2*>(&h[0]));
    float2 hi = __half22float2(*reinterpret_cast<__half2*>(&h[1]));
    f[0] += lo.x; f[1] += lo.y; f[2] += hi.x; f[3] += hi.y;
    h[0] = 0u; h[1] = 0u;
}

__device__ __forceinline__ uint2 cvt2h(float4 v) {
    __half2 p0 = __floats2half2_rn(v.x, v.y);
    __half2 p1 = __floats2half2_rn(v.z, v.w);
    return make_uint2(*reinterpret_cast<unsigned*>(&p0), *reinterpret_cast<unsigned*>(&p1));
}

// ---------------- k0: zero accumulators ------------------------------------
__global__ void k0_zero() {
    int t = blockIdx.x * 256 + threadIdx.x;
    if (t < B_ * K_) g_ssum[t] = 0.f;
    if (t < B_)      g_bnorm[t] = 0.f;
}

// ---------------- k1: logits mma(f16-acc) + softmax + ssum ------------------
// CTA 64k x 256n; W whole in smem; desc chunks 32d x 256n, 2 buffers.
// Warp w owns n-slice [w*32, w*32+32), all 64 k -> warp-local softmax.
// f16 accumulate within a 32-d chunk, promote to f32 per chunk.
#define K1_WSTR 1040
#define K1_DSTR 528
#define K1_SMW  0
#define K1_SMD  66560
#define K1_SMEM 100352

__global__ __launch_bounds__(256, 2)
void k1_mma(const float* __restrict__ desc, const float* __restrict__ W,
            const float* __restrict__ bias)
{
    extern __shared__ char smem[];
    __shared__ float sSum[64];
    const int b = blockIdx.y, n0 = blockIdx.x * 256;
    const int t = threadIdx.x, lane = t & 31, w = t >> 5;
    const float* __restrict__ dB = desc + (size_t)b * D_ * N_;
    if (t < 64) sSum[t] = 0.f;

    const unsigned sWu = smem_u32(smem) + K1_SMW;
    const unsigned sDu = smem_u32(smem) + K1_SMD;

    // preload whole W fp32 -> fp16 smem [64 k][512 d]
    #pragma unroll 4
    for (int r = 0; r < 32; r++) {
        int idx = r * 256 + t;
        int row = idx >> 7, c4 = idx & 127;
        float4 v = *reinterpret_cast<const float4*>(W + row * D_ + c4 * 4);
        *reinterpret_cast<uint2*>(smem + K1_SMW + row * K1_WSTR + c4 * 8) = cvt2h(v);
    }
    // desc chunk 0
    #pragma unroll
    for (int r = 0; r < 8; r++) {
        int idx = r * 256 + t;
        int dc = idx >> 6, n4 = idx & 63;
        float4 v = *reinterpret_cast<const float4*>(dB + (size_t)dc * N_ + n0 + n4 * 4);
        *reinterpret_cast<uint2*>(smem + K1_SMD + dc * K1_DSTR + n4 * 8) = cvt2h(v);
    }
    __syncthreads();

    float acc[4][4][4];
    unsigned hacc[4][4][2];
    #pragma unroll
    for (int mt = 0; mt < 4; mt++)
        #pragma unroll
        for (int nt = 0; nt < 4; nt++) {
            hacc[mt][nt][0] = 0u; hacc[mt][nt][1] = 0u;
            #pragma unroll
            for (int q = 0; q < 4; q++) acc[mt][nt][q] = 0.f;
        }

    const int aRow = (lane & 7) + ((lane >> 3) & 1) * 8;
    const int aK   = ((lane >> 4) & 1) * 16;
    const int bDr  = ((lane >> 3) & 1) * 8 + (lane & 7);
    const int bN   = ((lane >> 4) & 1) * 8;
    const int pdc  = t >> 6, pn4 = t & 63;

    #pragma unroll 1
    for (int c = 0; c < 16; c++) {
        float4 nx[8];
        if (c < 15) {
            #pragma unroll
            for (int r = 0; r < 8; r++) {
                int dc = (c + 1) * 32 + r * 4 + pdc;
                nx[r] = *reinterpret_cast<const float4*>(dB + (size_t)dc * N_ + n0 + pn4 * 4);
            }
        }
        const unsigned sDb = sDu + (unsigned)(c & 1) * 16896u;
        #pragma unroll
        for (int ks = 0; ks < 2; ks++) {
            unsigned af[4][4];
            #pragma unroll
            for (int mt = 0; mt < 4; mt++)
                LDMX4(af[mt], sWu + (mt * 16 + aRow) * K1_WSTR + (c * 32 + ks * 16) * 2 + aK);
            unsigned bfr[2][4];
            #pragma unroll
            for (int np = 0; np < 2; np++)
                LDMX4T(bfr[np], sDb + (ks * 16 + bDr) * K1_DSTR + (w * 32 + np * 16 + bN) * 2);
            #pragma unroll
            for (int mt = 0; mt < 4; mt++)
                #pragma unroll
                for (int nt = 0; nt < 4; nt++)
                    MMAH(hacc[mt][nt], af[mt],
                         bfr[nt >> 1][(nt & 1) * 2], bfr[nt >> 1][(nt & 1) * 2 + 1]);
        }
        // promote chunk partials (32 d) into f32
        #pragma unroll
        for (int mt = 0; mt < 4; mt++)
            #pragma unroll
            for (int nt = 0; nt < 4; nt++)
                promo(acc[mt][nt], hacc[mt][nt]);
        if (c < 15) {
            const unsigned off = K1_SMD + (unsigned)((c + 1) & 1) * 16896u;
            #pragma unroll
            for (int r = 0; r < 8; r++) {
                int dc = r * 4 + pdc;
                *reinterpret_cast<uint2*>(smem + off + dc * K1_DSTR + pn4 * 8) = cvt2h(nx[r]);
            }
        }
        __syncthreads();
    }

    // ---- warp-local softmax over 64 k ----
    const int g = lane >> 2, cl = lane & 3;
    #pragma unroll
    for (int mt = 0; mt < 4; mt++) {
        float b0v = __ldg(bias + mt * 16 + g);
        float b1v = __ldg(bias + mt * 16 + g + 8);
        #pragma unroll
        for (int nt = 0; nt < 4; nt++) {
            acc[mt][nt][0] += b0v; acc[mt][nt][1] += b0v;
            acc[mt][nt][2] += b1v; acc[mt][nt][3] += b1v;
        }
    }
    #pragma unroll
    for (int nt = 0; nt < 4; nt++) {
        #pragma unroll
        for (int par = 0; par < 2; par++) {
            float m = fmaxf(acc[0][nt][par], acc[0][nt][2 + par]);
            #pragma unroll
            for (int mt = 1; mt < 4; mt++)
                m = fmaxf(m, fmaxf(acc[mt][nt][par], acc[mt][nt][2 + par]));
            #pragma unroll
            for (int o = 4; o <= 16; o <<= 1)
                m = fmaxf(m, __shfl_xor_sync(0xffffffffu, m, o));
            float s = 0.f;
            #pragma unroll
            for (int mt = 0; mt < 4; mt++) {
                float e0 = __expf(acc[mt][nt][par]     - m);
                float e1 = __expf(acc[mt][nt][2 + par] - m);
                acc[mt][nt][par] = e0; acc[mt][nt][2 + par] = e1;
                s += e0 + e1;
            }
            #pragma unroll
            for (int o = 4; o <= 16; o <<= 1)
                s += __shfl_xor_sync(0xffffffffu, s, o);
            float inv = 1.f / s;
            #pragma unroll
            for (int mt = 0; mt < 4; mt++) {
                acc[mt][nt][par]     *= inv;
                acc[mt][nt][2 + par] *= inv;
            }
        }
    }
    #pragma unroll
    for (int mt = 0; mt < 4; mt++) {
        #pragma unroll
        for (int h = 0; h < 2; h++) {
            float s = 0.f;
            #pragma unroll
            for (int nt = 0; nt < 4; nt++)
                s += acc[mt][nt][h * 2] + acc[mt][nt][h * 2 + 1];
            s += __shfl_xor_sync(0xffffffffu, s, 1);
            s += __shfl_xor_sync(0xffffffffu, s, 2);
            if (cl == 0) atomicAdd(&sSum[mt * 16 + g + h * 8], s);
        }
    }
    // stage S fp16 [64 k][528B rows] in desc-buffer region
    #pragma unroll
    for (int mt = 0; mt < 4; mt++) {
        #pragma unroll
        for (int h = 0; h < 2; h++) {
            int k = mt * 16 + g + h * 8;
            #pragma unroll
            for (int nt = 0; nt < 4; nt++) {
                __half2 p = __floats2half2_rn(acc[mt][nt][h * 2], acc[mt][nt][h * 2 + 1]);
                *reinterpret_cast<unsigned*>(
                    smem + K1_SMD + k * K1_DSTR + (w * 32 + nt * 8 + cl * 2) * 2) =
                    *reinterpret_cast<unsigned*>(&p);
            }
        }
    }
    __syncthreads();
    __half* Sb = g_Shf + (size_t)b * K_ * N_ + n0;
    #pragma unroll
    for (int r = 0; r < 8; r++) {
        int idx = r * 256 + t;
        int k = idx >> 5, c16 = idx & 31;
        uint4 v = *reinterpret_cast<const uint4*>(smem + K1_SMD + k * K1_DSTR + c16 * 16);
        *reinterpret_cast<uint4*>(Sb + (size_t)k * N_ + c16 * 8) = v;
    }
    if (t < 64) atomicAdd(&g_ssum[b * K_ + t], sSum[t]);
}

// ---------------- k2: agg mma(f16-acc), double-buffered, fp16 slabs ---------
#define K2_STR  144
#define K2_SMA  0
#define K2_SMB  36864
#define K2_SMEM 55296

__global__ __launch_bounds__(256, 2)
void k2_mma(const float* __restrict__ desc)
{
    extern __shared__ char smem[];
    const int t = threadIdx.x, lane = t & 31, w = t >> 5;
    const int warpM = w >> 1, warpN = w & 1;
    const int d0 = blockIdx.x * 128, ns = blockIdx.y, b = blockIdx.z;
    const int nbase = ns * (N_ / NSPLIT);

    const float* __restrict__ dB = desc + (size_t)b * D_ * N_;
    const __half* __restrict__ Sb = g_Shf + (size_t)b * K_ * N_;

    const unsigned sAu = smem_u32(smem) + K2_SMA;
    const unsigned sBu = smem_u32(smem) + K2_SMB;

    const int paR = t >> 4, pa4 = t & 15;
    const int pbR = t >> 3, pb16 = t & 7;

    {
        #pragma unroll
        for (int r = 0; r < 8; r++) {
            int row = r * 16 + paR;
            float4 v = *reinterpret_cast<const float4*>(
                dB + (size_t)(d0 + row) * N_ + nbase + pa4 * 4);
            *reinterpret_cast<uint2*>(smem + K2_SMA + row * K2_STR + pa4 * 8) = cvt2h(v);
        }
        #pragma unroll
        for (int r = 0; r < 2; r++) {
            int row = r * 32 + pbR;
            uint4 v = *reinterpret_cast<const uint4*>(Sb + (size_t)row * N_ + nbase + pb16 * 8);
            *reinterpret_cast<uint4*>(smem + K2_SMB + row * K2_STR + pb16 * 16) = v;
        }
    }
    __syncthreads();

    float acc[2][4][4];
    unsigned hacc[2][4][2];
    #pragma unroll
    for (int mt = 0; mt < 2; mt++)
        #pragma unroll
        for (int nt = 0; nt < 4; nt++) {
            hacc[mt][nt][0] = 0u; hacc[mt][nt][1] = 0u;
            #pragma unroll
            for (int q = 0; q < 4; q++) acc[mt][nt][q] = 0.f;
        }

    const int aRow = (lane & 7) + ((lane >> 3) & 1) * 8;
    const int aK   = ((lane >> 4) & 1) * 16;
    const int bRow = (lane & 7) + ((lane >> 4) & 1) * 8;
    const int bK   = ((lane >> 3) & 1) * 16;

    #pragma unroll 1
    for (int c = 0; c < 16; c++) {
        float4 nxA[8];
        uint4  nxB[2];
        if (c < 15) {
            const int n0c = nbase + (c + 1) * 64;
            #pragma unroll
            for (int r = 0; r < 8; r++) {
                int row = r * 16 + paR;
                nxA[r] = *reinterpret_cast<const float4*>(
                    dB + (size_t)(d0 + row) * N_ + n0c + pa4 * 4);
            }
            #pragma unroll
            for (int r = 0; r < 2; r++) {
                int row = r * 32 + pbR;
                nxB[r] = *reinterpret_cast<const uint4*>(Sb + (size_t)row * N_ + n0c + pb16 * 8);
            }
        }
        const unsigned offA = (unsigned)(c & 1) * 18432u;
        const unsigned offB = (unsigned)(c & 1) * 9216u;
        #pragma unroll
        for (int ks = 0; ks < 4; ks++) {
            unsigned af[2][4];
            #pragma unroll
            for (int mt = 0; mt < 2; mt++)
                LDMX4(af[mt], sAu + offA + (warpM * 32 + mt * 16 + aRow) * K2_STR
                              + ks * 32 + aK);
            unsigned bfr[2][4];
            #pragma unroll
            for (int np = 0; np < 2; np++)
                LDMX4(bfr[np], sBu + offB + (warpN * 32 + np * 16 + bRow) * K2_STR
                               + ks * 32 + bK);
            #pragma unroll
            for (int mt = 0; mt < 2; mt++)
                #pragma unroll
                for (int nt = 0; nt < 4; nt++)
                    MMAH(hacc[mt][nt], af[mt],
                         bfr[nt >> 1][(nt & 1) * 2], bfr[nt >> 1][(nt & 1) * 2 + 1]);
        }
        // promote chunk partials (64 n) into f32
        #pragma unroll
        for (int mt = 0; mt < 2; mt++)
            #pragma unroll
            for (int nt = 0; nt < 4; nt++)
                promo(acc[mt][nt], hacc[mt][nt]);
        if (c < 15) {
            const unsigned dA = K2_SMA + (unsigned)((c + 1) & 1) * 18432u;
            const unsigned dBo = K2_SMB + (unsigned)((c + 1) & 1) * 9216u;
            #pragma unroll
            for (int r = 0; r < 8; r++) {
                int row = r * 16 + paR;
                *reinterpret_cast<uint2*>(smem + dA + row * K2_STR + pa4 * 8) = cvt2h(nxA[r]);
            }
            #pragma unroll
            for (int r = 0; r < 2; r++) {
                int row = r * 32 + pbR;
                *reinterpret_cast<uint4*>(smem + dBo + row * K2_STR + pb16 * 16) = nxB[r];
            }
        }
        __syncthreads();
    }

    // epilogue: fp16 slab stores
    __half* outp = g_parth + ((size_t)ns * B_ + b) * (D_ * K_);
    const int dBase = d0 + warpM * 32 + (lane >> 2);
    const int kBase = warpN * 32 + (lane & 3) * 2;
    #pragma unroll
    for (int mt = 0; mt < 2; mt++) {
        #pragma unroll
        for (int nt = 0; nt < 4; nt++) {
            int k = kBase + nt * 8;
            int d = dBase + mt * 16;
            __half2 p0 = __floats2half2_rn(acc[mt][nt][0], acc[mt][nt][1]);
            __half2 p1 = __floats2half2_rn(acc[mt][nt][2], acc[mt][nt][3]);
            *reinterpret_cast<unsigned*>(outp + (size_t)d * K_ + k) =
                *reinterpret_cast<unsigned*>(&p0);
            *reinterpret_cast<unsigned*>(outp + (size_t)(d + 8) * K_ + k) =
                *reinterpret_cast<unsigned*>(&p1);
        }
    }
}

// ---------------- k3: sum 4 fp16 slabs, subtract centers*ssum, intra-norm ---
__global__ void k3_vlad(const float* __restrict__ centers, float* __restrict__ out)
{
    const int b  = blockIdx.x;
    const int k8 = blockIdx.y * 8;
    const int t  = threadIdx.x;

    float ss[8];
    {
        float4 s0 = *reinterpret_cast<const float4*>(&g_ssum[b * K_ + k8]);
        float4 s1 = *reinterpret_cast<const float4*>(&g_ssum[b * K_ + k8 + 4]);
        ss[0]=s0.x; ss[1]=s0.y; ss[2]=s0.z; ss[3]=s0.w;
        ss[4]=s1.x; ss[5]=s1.y; ss[6]=s1.z; ss[7]=s1.w;
    }

    float v[2][8];
    float sq[8];
    #pragma unroll
    for (int i = 0; i < 8; i++) sq[i] = 0.f;

    #pragma unroll
    for (int rr = 0; rr < 2; rr++) {
        const int d = t + rr * 256;
        float a[8];
        #pragma unroll
        for (int i = 0; i < 8; i++) a[i] = 0.f;
        #pragma unroll
        for (int s = 0; s < NSPLIT; s++) {
            uint4 u = *reinterpret_cast<const uint4*>(
                g_parth + ((size_t)s * B_ + b) * (D_ * K_) + (size_t)d * K_ + k8);
            const __half2* h = reinterpret_cast<const __half2*>(&u);
            #pragma unroll
            for (int j = 0; j < 4; j++) {
                float2 f = __half22float2(h[j]);
                a[2 * j]     += f.x;
                a[2 * j + 1] += f.y;
            }
        }
        float4 c0 = *reinterpret_cast<const float4*>(&centers[(size_t)d * K_ + k8]);
        float4 c1 = *reinterpret_cast<const float4*>(&centers[(size_t)d * K_ + k8 + 4]);
        float cc[8] = {c0.x, c0.y, c0.z, c0.w, c1.x, c1.y, c1.z, c1.w};
        #pragma unroll
        for (int i = 0; i < 8; i++) {
            float vv = a[i] - cc[i] * ss[i];
            v[rr][i] = vv;
            sq[i] += vv * vv;
        }
    }

    __shared__ float4 red[256][2];
    __shared__ float sinvv[8];
    red[t][0] = make_float4(sq[0], sq[1], sq[2], sq[3]);
    red[t][1] = make_float4(sq[4], sq[5], sq[6], sq[7]);
    __syncthreads();
    #pragma unroll
    for (int s = 128; s >= 1; s >>= 1) {
        if (t < s) {
            float4 o0 = red[t + s][0], o1 = red[t + s][1];
            red[t][0].x += o0.x; red[t][0].y += o0.y; red[t][0].z += o0.z; red[t][0].w += o0.w;
            red[t][1].x += o1.x; red[t][1].y += o1.y; red[t][1].z += o1.z; red[t][1].w += o1.w;
        }
        __syncthreads();
    }
    if (t == 0) {
        float tot[8] = {red[0][0].x, red[0][0].y, red[0][0].z, red[0][0].w,
                        red[0][1].x, red[0][1].y, red[0][1].z, red[0][1].w};
        float bn = 0.f;
        #pragma unroll
        for (int i = 0; i < 8; i++) {
            float inv = 1.f / fmaxf(sqrtf(tot[i]), 1e-12f);
            sinvv[i] = inv;
            bn += tot[i] * inv * inv;
        }
        atomicAdd(&g_bnorm[b], bn);
    }
    __syncthreads();

    float* ob = out + (size_t)b * (D_ * K_);
    #pragma unroll
    for (int rr = 0; rr < 2; rr++) {
        const int d = t + rr * 256;
        float4 o0, o1;
        o0.x = v[rr][0] * sinvv[0]; o0.y = v[rr][1] * sinvv[1];
        o0.z = v[rr][2] * sinvv[2]; o0.w = v[rr][3] * sinvv[3];
        o1.x = v[rr][4] * sinvv[4]; o1.y = v[rr][5] * sinvv[5];
        o1.z = v[rr][6] * sinvv[6]; o1.w = v[rr][7] * sinvv[7];
        *reinterpret_cast<float4*>(&ob[(size_t)d * K_ + k8])     = o0;
        *reinterpret_cast<float4*>(&ob[(size_t)d * K_ + k8 + 4]) = o1;
    }
}

// ---------------- k4: global L2 normalize (float4) --------------------------
__global__ void k4_gnorm(float4* __restrict__ out4)
{
    const int blk = blockIdx.x;
    const float bn = g_bnorm[blk >> 4];
    const float inv = 1.f / fmaxf(sqrtf(bn), 1e-12f);
    int base = blk * 512 + threadIdx.x;
    #pragma unroll
    for (int r = 0; r < 2; r++) {
        float4 v = out4[base + r * 256];
        v.x *= inv; v.y *= inv; v.z *= inv; v.w *= inv;
        out4[base + r * 256] = v;
    }
}

// ---------------- launch -----------------------------------------------------
extern "C" void kernel_launch(void* const* d_in, const int* in_sizes, int n_in,
                              void* d_out, int out_size)
{
    const float* desc    = (const float*)d_in[0];   // [16,512,4096]
    const float* W       = (const float*)d_in[1];   // [64,512]
    const float* bias    = (const float*)d_in[2];   // [64]
    const float* centers = (const float*)d_in[3];   // [512,64]
    float* out = (float*)d_out;                      // [16, 512*64]

    cudaFuncSetAttribute(k1_mma, cudaFuncAttributeMaxDynamicSharedMemorySize, K1_SMEM);
    cudaFuncSetAttribute(k2_mma, cudaFuncAttributeMaxDynamicSharedMemorySize, K2_SMEM);

    k0_zero<<<4, 256>>>();
    k1_mma<<<dim3(N_ / 256, B_), 256, K1_SMEM>>>(desc, W, bias);
    k2_mma<<<dim3(D_ / 128, NSPLIT, B_), 256, K2_SMEM>>>(desc);
    k3_vlad<<<dim3(B_, 8), 256>>>(centers, out);
    k4_gnorm<<<256, 256>>>((float4*)out);
}

// round 11
// speedup vs baseline: 1.2858x; 1.2858x over previous
#include <cuda_runtime.h>
#include <cuda_bf16.h>
#include <math.h>
#include <stdint.h>

#define B_ 16
#define D_ 512
#define K_ 64
#define N_ 4096
#define NSPLIT 4

// ---------------- scratch -----------------------------------------------------
__device__ __nv_bfloat16 g_Sbf[(size_t)B_ * K_ * N_];            // softmax scores bf16 [b][k][n]
__device__ __nv_bfloat16 g_partb[(size_t)NSPLIT * B_ * D_ * K_]; // agg partials bf16 [ns][b][d][k]
__device__ float g_ssum_p[16][B_][K_];                           // per-nchunk ssum partials
__device__ float g_bnorm_p[B_][8];                               // per-kgroup bnorm partials

__device__ __forceinline__ unsigned smem_u32(const void* p) {
    unsigned a;
    asm("{ .reg .u64 t; cvta.to.shared.u64 t, %1; cvt.u32.u64 %0, t; }" : "=r"(a) : "l"(p));
    return a;
}

#define LDMX4(dst, addr) \
    asm volatile("ldmatrix.sync.aligned.m8n8.x4.shared.b16 {%0,%1,%2,%3}, [%4];" \
        : "=r"((dst)[0]), "=r"((dst)[1]), "=r"((dst)[2]), "=r"((dst)[3]) : "r"(addr))
#define LDMX4T(dst, addr) \
    asm volatile("ldmatrix.sync.aligned.m8n8.x4.trans.shared.b16 {%0,%1,%2,%3}, [%4];" \
        : "=r"((dst)[0]), "=r"((dst)[1]), "=r"((dst)[2]), "=r"((dst)[3]) : "r"(addr))
#define MMA16816(acc, a, b0, b1) \
    asm volatile("mma.sync.aligned.m16n8k16.row.col.f32.bf16.bf16.f32 " \
        "{%0,%1,%2,%3}, {%4,%5,%6,%7}, {%8,%9}, {%0,%1,%2,%3};" \
        : "+f"((acc)[0]), "+f"((acc)[1]), "+f"((acc)[2]), "+f"((acc)[3]) \
        : "r"((a)[0]), "r"((a)[1]), "r"((a)[2]), "r"((a)[3]), "r"(b0), "r"(b1))

__device__ __forceinline__ uint2 cvt2(float4 v) {
    __nv_bfloat162 p0 = __floats2bfloat162_rn(v.x, v.y);
    __nv_bfloat162 p1 = __floats2bfloat162_rn(v.z, v.w);
    return make_uint2(*reinterpret_cast<unsigned*>(&p0), *reinterpret_cast<unsigned*>(&p1));
}

// ---------------- k1: logits mma + softmax + ssum, double-buffered ----------
// CTA 64k x 256n; W whole in smem; desc chunks 32d x 256n, 2 buffers.
// Warp w owns n-slice [w*32, w*32+32), all 64 k -> warp-local softmax.
#define K1_WSTR 1040     // 512 d bf16 + 16 pad
#define K1_DSTR 528      // 256 n bf16 + 16 pad
#define K1_SMW  0        // 64*1040 = 66560
#define K1_SMD  66560    // 2 * 32*528 = 33792 (also S staging [64][528])
#define K1_SMEM 100352

__global__ __launch_bounds__(256, 2)
void k1_mma(const float* __restrict__ desc, const float* __restrict__ W,
            const float* __restrict__ bias)
{
    extern __shared__ char smem[];
    __shared__ float sSum[64];
    const int b = blockIdx.y, n0 = blockIdx.x * 256;
    const int t = threadIdx.x, lane = t & 31, w = t >> 5;
    const float* __restrict__ dB = desc + (size_t)b * D_ * N_;
    if (t < 64) sSum[t] = 0.f;

    const unsigned sWu = smem_u32(smem) + K1_SMW;
    const unsigned sDu = smem_u32(smem) + K1_SMD;

    // preload whole W fp32 -> bf16 smem [64 k][512 d]
    #pragma unroll 4
    for (int r = 0; r < 32; r++) {
        int idx = r * 256 + t;
        int row = idx >> 7, c4 = idx & 127;
        float4 v = *reinterpret_cast<const float4*>(W + row * D_ + c4 * 4);
        *reinterpret_cast<uint2*>(smem + K1_SMW + row * K1_WSTR + c4 * 8) = cvt2(v);
    }
    // desc chunk 0
    #pragma unroll
    for (int r = 0; r < 8; r++) {
        int idx = r * 256 + t;
        int dc = idx >> 6, n4 = idx & 63;
        float4 v = *reinterpret_cast<const float4*>(dB + (size_t)dc * N_ + n0 + n4 * 4);
        *reinterpret_cast<uint2*>(smem + K1_SMD + dc * K1_DSTR + n4 * 8) = cvt2(v);
    }
    __syncthreads();

    float acc[4][4][4];
    #pragma unroll
    for (int mt = 0; mt < 4; mt++)
        #pragma unroll
        for (int nt = 0; nt < 4; nt++)
            #pragma unroll
            for (int q = 0; q < 4; q++) acc[mt][nt][q] = 0.f;

    const int aRow = (lane & 7) + ((lane >> 3) & 1) * 8;
    const int aK   = ((lane >> 4) & 1) * 16;
    const int bDr  = ((lane >> 3) & 1) * 8 + (lane & 7);
    const int bN   = ((lane >> 4) & 1) * 8;
    const int pdc  = t >> 6, pn4 = t & 63;

    #pragma unroll 1
    for (int c = 0; c < 16; c++) {
        float4 nx[8];
        if (c < 15) {
            #pragma unroll
            for (int r = 0; r < 8; r++) {
                int dc = (c + 1) * 32 + r * 4 + pdc;
                nx[r] = *reinterpret_cast<const float4*>(dB + (size_t)dc * N_ + n0 + pn4 * 4);
            }
        }
        const unsigned sDb = sDu + (unsigned)(c & 1) * 16896u;
        #pragma unroll
        for (int ks = 0; ks < 2; ks++) {
            unsigned af[4][4];
            #pragma unroll
            for (int mt = 0; mt < 4; mt++)
                LDMX4(af[mt], sWu + (mt * 16 + aRow) * K1_WSTR + (c * 32 + ks * 16) * 2 + aK);
            unsigned bfr[2][4];
            #pragma unroll
            for (int np = 0; np < 2; np++)
                LDMX4T(bfr[np], sDb + (ks * 16 + bDr) * K1_DSTR + (w * 32 + np * 16 + bN) * 2);
            #pragma unroll
            for (int mt = 0; mt < 4; mt++)
                #pragma unroll
                for (int nt = 0; nt < 4; nt++)
                    MMA16816(acc[mt][nt], af[mt],
                             bfr[nt >> 1][(nt & 1) * 2], bfr[nt >> 1][(nt & 1) * 2 + 1]);
        }
        if (c < 15) {
            const unsigned off = K1_SMD + (unsigned)((c + 1) & 1) * 16896u;
            #pragma unroll
            for (int r = 0; r < 8; r++) {
                int dc = r * 4 + pdc;
                *reinterpret_cast<uint2*>(smem + off + dc * K1_DSTR + pn4 * 8) = cvt2(nx[r]);
            }
        }
        __syncthreads();
    }

    // ---- warp-local softmax over 64 k ----
    const int g = lane >> 2, cl = lane & 3;
    #pragma unroll
    for (int mt = 0; mt < 4; mt++) {
        float b0v = __ldg(bias + mt * 16 + g);
        float b1v = __ldg(bias + mt * 16 + g + 8);
        #pragma unroll
        for (int nt = 0; nt < 4; nt++) {
            acc[mt][nt][0] += b0v; acc[mt][nt][1] += b0v;
            acc[mt][nt][2] += b1v; acc[mt][nt][3] += b1v;
        }
    }
    #pragma unroll
    for (int nt = 0; nt < 4; nt++) {
        #pragma unroll
        for (int par = 0; par < 2; par++) {
            float m = fmaxf(acc[0][nt][par], acc[0][nt][2 + par]);
            #pragma unroll
            for (int mt = 1; mt < 4; mt++)
                m = fmaxf(m, fmaxf(acc[mt][nt][par], acc[mt][nt][2 + par]));
            #pragma unroll
            for (int o = 4; o <= 16; o <<= 1)
                m = fmaxf(m, __shfl_xor_sync(0xffffffffu, m, o));
            float s = 0.f;
            #pragma unroll
            for (int mt = 0; mt < 4; mt++) {
                float e0 = __expf(acc[mt][nt][par]     - m);
                float e1 = __expf(acc[mt][nt][2 + par] - m);
                acc[mt][nt][par] = e0; acc[mt][nt][2 + par] = e1;
                s += e0 + e1;
            }
            #pragma unroll
            for (int o = 4; o <= 16; o <<= 1)
                s += __shfl_xor_sync(0xffffffffu, s, o);
            float inv = 1.f / s;
            #pragma unroll
            for (int mt = 0; mt < 4; mt++) {
                acc[mt][nt][par]     *= inv;
                acc[mt][nt][2 + par] *= inv;
            }
        }
    }
    // ssum per k (warp's 32 n) -> smem atomics (block-local)
    #pragma unroll
    for (int mt = 0; mt < 4; mt++) {
        #pragma unroll
        for (int h = 0; h < 2; h++) {
            float s = 0.f;
            #pragma unroll
            for (int nt = 0; nt < 4; nt++)
                s += acc[mt][nt][h * 2] + acc[mt][nt][h * 2 + 1];
            s += __shfl_xor_sync(0xffffffffu, s, 1);
            s += __shfl_xor_sync(0xffffffffu, s, 2);
            if (cl == 0) atomicAdd(&sSum[mt * 16 + g + h * 8], s);
        }
    }
    // stage S bf16 [64 k][528B rows] in desc-buffer region
    #pragma unroll
    for (int mt = 0; mt < 4; mt++) {
        #pragma unroll
        for (int h = 0; h < 2; h++) {
            int k = mt * 16 + g + h * 8;
            #pragma unroll
            for (int nt = 0; nt < 4; nt++) {
                __nv_bfloat162 p = __floats2bfloat162_rn(acc[mt][nt][h * 2],
                                                         acc[mt][nt][h * 2 + 1]);
                *reinterpret_cast<unsigned*>(
                    smem + K1_SMD + k * K1_DSTR + (w * 32 + nt * 8 + cl * 2) * 2) =
                    *reinterpret_cast<unsigned*>(&p);
            }
        }
    }
    __syncthreads();
    __nv_bfloat16* Sb = g_Sbf + (size_t)b * K_ * N_ + n0;
    #pragma unroll
    for (int r = 0; r < 8; r++) {
        int idx = r * 256 + t;
        int k = idx >> 5, c16 = idx & 31;
        uint4 v = *reinterpret_cast<const uint4*>(smem + K1_SMD + k * K1_DSTR + c16 * 16);
        *reinterpret_cast<uint4*>(Sb + (size_t)k * N_ + c16 * 8) = v;
    }
    // per-chunk ssum partials: no atomics, no zero-init needed
    if (t < 64) g_ssum_p[blockIdx.x][b][t] = sSum[t];
}

// ---------------- k2: agg mma, double-buffered, bf16 slabs ------------------
#define K2_STR  144
#define K2_SMA  0
#define K2_SMB  36864
#define K2_SMEM 55296

__global__ __launch_bounds__(256, 2)
void k2_mma(const float* __restrict__ desc)
{
    extern __shared__ char smem[];
    const int t = threadIdx.x, lane = t & 31, w = t >> 5;
    const int warpM = w >> 1, warpN = w & 1;
    const int d0 = blockIdx.x * 128, ns = blockIdx.y, b = blockIdx.z;
    const int nbase = ns * (N_ / NSPLIT);

    const float* __restrict__ dB = desc + (size_t)b * D_ * N_;
    const __nv_bfloat16* __restrict__ Sb = g_Sbf + (size_t)b * K_ * N_;

    const unsigned sAu = smem_u32(smem) + K2_SMA;
    const unsigned sBu = smem_u32(smem) + K2_SMB;

    const int paR = t >> 4, pa4 = t & 15;
    const int pbR = t >> 3, pb16 = t & 7;

    {
        #pragma unroll
        for (int r = 0; r < 8; r++) {
            int row = r * 16 + paR;
            float4 v = *reinterpret_cast<const float4*>(
                dB + (size_t)(d0 + row) * N_ + nbase + pa4 * 4);
            *reinterpret_cast<uint2*>(smem + K2_SMA + row * K2_STR + pa4 * 8) = cvt2(v);
        }
        #pragma unroll
        for (int r = 0; r < 2; r++) {
            int row = r * 32 + pbR;
            uint4 v = *reinterpret_cast<const uint4*>(Sb + (size_t)row * N_ + nbase + pb16 * 8);
            *reinterpret_cast<uint4*>(smem + K2_SMB + row * K2_STR + pb16 * 16) = v;
        }
    }
    __syncthreads();

    float acc[2][4][4];
    #pragma unroll
    for (int mt = 0; mt < 2; mt++)
        #pragma unroll
        for (int nt = 0; nt < 4; nt++)
            #pragma unroll
            for (int q = 0; q < 4; q++) acc[mt][nt][q] = 0.f;

    const int aRow = (lane & 7) + ((lane >> 3) & 1) * 8;
    const int aK   = ((lane >> 4) & 1) * 16;
    const int bRow = (lane & 7) + ((lane >> 4) & 1) * 8;
    const int bK   = ((lane >> 3) & 1) * 16;

    #pragma unroll 1
    for (int c = 0; c < 16; c++) {
        float4 nxA[8];
        uint4  nxB[2];
        if (c < 15) {
            const int n0c = nbase + (c + 1) * 64;
            #pragma unroll
            for (int r = 0; r < 8; r++) {
                int row = r * 16 + paR;
                nxA[r] = *reinterpret_cast<const float4*>(
                    dB + (size_t)(d0 + row) * N_ + n0c + pa4 * 4);
            }
            #pragma unroll
            for (int r = 0; r < 2; r++) {
                int row = r * 32 + pbR;
                nxB[r] = *reinterpret_cast<const uint4*>(Sb + (size_t)row * N_ + n0c + pb16 * 8);
            }
        }
        const unsigned offA = (unsigned)(c & 1) * 18432u;
        const unsigned offB = (unsigned)(c & 1) * 9216u;
        #pragma unroll
        for (int ks = 0; ks < 4; ks++) {
            unsigned af[2][4];
            #pragma unroll
            for (int mt = 0; mt < 2; mt++)
                LDMX4(af[mt], sAu + offA + (warpM * 32 + mt * 16 + aRow) * K2_STR
                              + ks * 32 + aK);
            unsigned bfr[2][4];
            #pragma unroll
            for (int np = 0; np < 2; np++)
                LDMX4(bfr[np], sBu + offB + (warpN * 32 + np * 16 + bRow) * K2_STR
                               + ks * 32 + bK);
            #pragma unroll
            for (int mt = 0; mt < 2; mt++)
                #pragma unroll
                for (int nt = 0; nt < 4; nt++)
                    MMA16816(acc[mt][nt], af[mt],
                             bfr[nt >> 1][(nt & 1) * 2], bfr[nt >> 1][(nt & 1) * 2 + 1]);
        }
        if (c < 15) {
            const unsigned dA = K2_SMA + (unsigned)((c + 1) & 1) * 18432u;
            const unsigned dBo = K2_SMB + (unsigned)((c + 1) & 1) * 9216u;
            #pragma unroll
            for (int r = 0; r < 8; r++) {
                int row = r * 16 + paR;
                *reinterpret_cast<uint2*>(smem + dA + row * K2_STR + pa4 * 8) = cvt2(nxA[r]);
            }
            #pragma unroll
            for (int r = 0; r < 2; r++) {
                int row = r * 32 + pbR;
                *reinterpret_cast<uint4*>(smem + dBo + row * K2_STR + pb16 * 16) = nxB[r];
            }
        }
        __syncthreads();
    }

    // epilogue: bf16 slab stores
    __nv_bfloat16* outp = g_partb + ((size_t)ns * B_ + b) * (D_ * K_);
    const int dBase = d0 + warpM * 32 + (lane >> 2);
    const int kBase = warpN * 32 + (lane & 3) * 2;
    #pragma unroll
    for (int mt = 0; mt < 2; mt++) {
        #pragma unroll
        for (int nt = 0; nt < 4; nt++) {
            int k = kBase + nt * 8;
            int d = dBase + mt * 16;
            __nv_bfloat162 p0 = __floats2bfloat162_rn(acc[mt][nt][0], acc[mt][nt][1]);
            __nv_bfloat162 p1 = __floats2bfloat162_rn(acc[mt][nt][2], acc[mt][nt][3]);
            *reinterpret_cast<unsigned*>(outp + (size_t)d * K_ + k) =
                *reinterpret_cast<unsigned*>(&p0);
            *reinterpret_cast<unsigned*>(outp + (size_t)(d + 8) * K_ + k) =
                *reinterpret_cast<unsigned*>(&p1);
        }
    }
}

// ---------------- k3: sum slabs + ssum partials, subtract, intra-norm -------
// grid (B_, 8), 512 threads: thread t owns d=t, block owns 8 k.
__global__ __launch_bounds__(512)
void k3_vlad(const float* __restrict__ centers, float* __restrict__ out)
{
    const int b = blockIdx.x, kg = blockIdx.y, k8 = kg * 8, t = threadIdx.x;
    __shared__ float sP[16][8];
    __shared__ float sSs[8];
    __shared__ float sInv[8];
    __shared__ float4 red[256][2];

    if (t < 128) sP[t >> 3][t & 7] = g_ssum_p[t >> 3][b][k8 + (t & 7)];
    __syncthreads();
    if (t < 8) {
        float s = 0.f;
        #pragma unroll
        for (int c = 0; c < 16; c++) s += sP[c][t];
        sSs[t] = s;
    }
    __syncthreads();

    const int d = t;
    float a[8];
    #pragma unroll
    for (int i = 0; i < 8; i++) a[i] = 0.f;
    #pragma unroll
    for (int s = 0; s < NSPLIT; s++) {
        uint4 u = *reinterpret_cast<const uint4*>(
            g_partb + ((size_t)s * B_ + b) * (D_ * K_) + (size_t)d * K_ + k8);
        const __nv_bfloat162* h = reinterpret_cast<const __nv_bfloat162*>(&u);
        #pragma unroll
        for (int j = 0; j < 4; j++) {
            float2 f = __bfloat1622float2(h[j]);
            a[2 * j]     += f.x;
            a[2 * j + 1] += f.y;
        }
    }
    float4 c0 = *reinterpret_cast<const float4*>(&centers[(size_t)d * K_ + k8]);
    float4 c1 = *reinterpret_cast<const float4*>(&centers[(size_t)d * K_ + k8 + 4]);
    float cc[8] = {c0.x, c0.y, c0.z, c0.w, c1.x, c1.y, c1.z, c1.w};
    float v[8], sq[8];
    #pragma unroll
    for (int i = 0; i < 8; i++) {
        v[i] = a[i] - cc[i] * sSs[i];
        sq[i] = v[i] * v[i];
    }

    // fold 512 -> 256, then tree
    if (t >= 256) {
        red[t - 256][0] = make_float4(sq[0], sq[1], sq[2], sq[3]);
        red[t - 256][1] = make_float4(sq[4], sq[5], sq[6], sq[7]);
    }
    __syncthreads();
    if (t < 256) {
        float4 o0 = red[t][0], o1 = red[t][1];
        red[t][0] = make_float4(sq[0] + o0.x, sq[1] + o0.y, sq[2] + o0.z, sq[3] + o0.w);
        red[t][1] = make_float4(sq[4] + o1.x, sq[5] + o1.y, sq[6] + o1.z, sq[7] + o1.w);
    }
    __syncthreads();
    #pragma unroll
    for (int s = 128; s >= 1; s >>= 1) {
        if (t < s) {
            float4 o0 = red[t + s][0], o1 = red[t + s][1];
            red[t][0].x += o0.x; red[t][0].y += o0.y; red[t][0].z += o0.z; red[t][0].w += o0.w;
            red[t][1].x += o1.x; red[t][1].y += o1.y; red[t][1].z += o1.z; red[t][1].w += o1.w;
        }
        __syncthreads();
    }
    if (t == 0) {
        float tot[8] = {red[0][0].x, red[0][0].y, red[0][0].z, red[0][0].w,
                        red[0][1].x, red[0][1].y, red[0][1].z, red[0][1].w};
        float bn = 0.f;
        #pragma unroll
        for (int i = 0; i < 8; i++) {
            float inv = 1.f / fmaxf(sqrtf(tot[i]), 1e-12f);
            sInv[i] = inv;
            bn += tot[i] * inv * inv;
        }
        g_bnorm_p[b][kg] = bn;
    }
    __syncthreads();

    float* ob = out + (size_t)b * (D_ * K_);
    float4 o0, o1;
    o0.x = v[0] * sInv[0]; o0.y = v[1] * sInv[1];
    o0.z = v[2] * sInv[2]; o0.w = v[3] * sInv[3];
    o1.x = v[4] * sInv[4]; o1.y = v[5] * sInv[5];
    o1.z = v[6] * sInv[6]; o1.w = v[7] * sInv[7];
    *reinterpret_cast<float4*>(&ob[(size_t)d * K_ + k8])     = o0;
    *reinterpret_cast<float4*>(&ob[(size_t)d * K_ + k8 + 4]) = o1;
}

// ---------------- k4: global L2 normalize (float4, sums bnorm partials) -----
__global__ void k4_gnorm(float4* __restrict__ out4)
{
    const int blk = blockIdx.x;            // 256 blocks, 512 float4 each
    const int b = blk >> 4;
    __shared__ float sInv;
    if (threadIdx.x == 0) {
        float s = 0.f;
        #pragma unroll
        for (int i = 0; i < 8; i++) s += g_bnorm_p[b][i];
        sInv = 1.f / fmaxf(sqrtf(s), 1e-12f);
    }
    __syncthreads();
    const float inv = sInv;
    int base = blk * 512 + threadIdx.x;
    #pragma unroll
    for (int r = 0; r < 2; r++) {
        float4 v = out4[base + r * 256];
        v.x *= inv; v.y *= inv; v.z *= inv; v.w *= inv;
        out4[base + r * 256] = v;
    }
}

// ---------------- launch -----------------------------------------------------
extern "C" void kernel_launch(void* const* d_in, const int* in_sizes, int n_in,
                              void* d_out, int out_size)
{
    const float* desc    = (const float*)d_in[0];   // [16,512,4096]
    const float* W       = (const float*)d_in[1];   // [64,512]
    const float* bias    = (const float*)d_in[2];   // [64]
    const float* centers = (const float*)d_in[3];   // [512,64]
    float* out = (float*)d_out;                      // [16, 512*64]

    cudaFuncSetAttribute(k1_mma, cudaFuncAttributeMaxDynamicSharedMemorySize, K1_SMEM);
    cudaFuncSetAttribute(k2_mma, cudaFuncAttributeMaxDynamicSharedMemorySize, K2_SMEM);

    k1_mma<<<dim3(N_ / 256, B_), 256, K1_SMEM>>>(desc, W, bias);
    k2_mma<<<dim3(D_ / 128, NSPLIT, B_), 256, K2_SMEM>>>(desc);
    k3_vlad<<<dim3(B_, 8), 512>>>(centers, out);
    k4_gnorm<<<256, 256>>>((float4*)out);
}